// round 3
// baseline (speedup 1.0000x reference)
#include <cuda_runtime.h>
#include <cstdint>
#include <cstddef>

// Problem dims (fixed by the reference)
#define Bt 1024
#define Tt 512
#define Ii 45
#define Hh 128
#define Oo 45

#define NB  7            // batch rows per CTA (8th lane is zero pad)
#define NTH 128          // threads per CTA (thread t owns hidden unit j = t)
#define NBLK ((Bt + NB - 1) / NB)   // 147 CTAs

// Shared-memory layout (in floats)
#define OFF_WHH  0                         // W_hh transposed: [k][j], 128*128
#define OFF_WIH  (Hh * Hh)                 // W_ih transposed: [i][j], 45*128
#define OFF_BIAS (OFF_WIH + Ii * Hh)       // b_ih + b_hh, 128
#define OFF_H    (OFF_BIAS + Hh)           // h double buffer: [2][128][8]
#define OFF_X    (OFF_H + 2 * Hh * 8)      // x stage double buffer: [2][48][8]
#define SMEM_FLOATS (OFF_X + 2 * 48 * 8)
#define SMEM_BYTES  (SMEM_FLOATS * 4)      // 100,352 bytes

typedef unsigned long long ull;

// Packed fp32x2 FMA (sm_100+): acc = a*b + acc, elementwise on 2 packed floats
__device__ __forceinline__ void fma2(ull& acc, ull a, ull b) {
    asm("fma.rn.f32x2 %0, %1, %2, %0;" : "+l"(acc) : "l"(a), "l"(b));
}
__device__ __forceinline__ ull pack2(float f) {
    ull d; unsigned u = __float_as_uint(f);
    asm("mov.b64 %0, {%1, %1};" : "=l"(d) : "r"(u));
    return d;
}
__device__ __forceinline__ float2 unpack2(ull d) {
    unsigned lo, hi;
    asm("mov.b64 {%0, %1}, %2;" : "=r"(lo), "=r"(hi) : "l"(d));
    return make_float2(__uint_as_float(lo), __uint_as_float(hi));
}

__global__ void __launch_bounds__(NTH, 1)
rnn_fused_kernel(const float* __restrict__ x,
                 const float* __restrict__ W_ih,
                 const float* __restrict__ b_ih,
                 const float* __restrict__ W_hh,
                 const float* __restrict__ b_hh,
                 const float* __restrict__ W_fc,
                 const float* __restrict__ b_fc,
                 float* __restrict__ out)
{
    extern __shared__ float sm[];
    float* whh_t  = sm + OFF_WHH;
    float* wih_t  = sm + OFF_WIH;
    float* bias_s = sm + OFF_BIAS;
    float* hT     = sm + OFF_H;     // [buf][k][b], b padded to 8 (lane 7 = 0)
    float* xT     = sm + OFF_X;     // [buf][i][b], i padded to 48, b padded to 8

    const int tid = threadIdx.x;
    const int rowBase = blockIdx.x * NB;

    // ---- Stage weights into SMEM (transposed for conflict-free inner loops) ----
    for (int idx = tid; idx < Hh * Hh; idx += NTH) {
        int jj = idx >> 7;
        int kk = idx & (Hh - 1);
        whh_t[kk * Hh + jj] = W_hh[idx];        // whh_t[k][j] = W_hh[j][k]
    }
    for (int idx = tid; idx < Hh * Ii; idx += NTH) {
        int jj = idx / Ii;
        int ii = idx - jj * Ii;
        wih_t[ii * Hh + jj] = W_ih[idx];        // wih_t[i][j] = W_ih[j][i]
    }
    if (tid < Hh) bias_s[tid] = b_ih[tid] + b_hh[tid];
    // Zero h (both buffers) and x (both buffers, incl. pad lanes)
    for (int idx = tid; idx < 2 * Hh * 8; idx += NTH) hT[idx] = 0.0f;
    for (int idx = tid; idx < 2 * 48 * 8; idx += NTH) xT[idx] = 0.0f;

    // ---- x stager: each thread owns up to 3 of the NB*Ii = 315 elements ----
    const int e0 = tid, e1 = tid + NTH, e2 = tid + 2 * NTH;
    const bool a0 = e0 < NB * Ii, a1 = e1 < NB * Ii, a2 = e2 < NB * Ii;
    const int b0 = e0 / Ii, b1 = e1 / Ii, b2 = e2 / Ii;
    const int i0 = e0 - b0 * Ii, i1 = e1 - b1 * Ii, i2 = e2 - b2 * Ii;
    const bool val0 = a0 && (rowBase + b0 < Bt);
    const bool val1 = a1 && (rowBase + b1 < Bt);
    const bool val2 = a2 && (rowBase + b2 < Bt);
    const float* g0 = x + ((size_t)(rowBase + b0) * Tt) * Ii + i0;
    const float* g1 = x + ((size_t)(rowBase + b1) * Tt) * Ii + i1;
    const float* g2 = x + ((size_t)(rowBase + b2) * Tt) * Ii + i2;
    const int s0 = i0 * 8 + b0, s1 = i1 * 8 + b1, s2 = i2 * 8 + b2;

    __syncthreads();   // zero-fill visible before first stage

    // Stage x for t = 0 into buffer 0
    if (a0) xT[s0] = val0 ? g0[0] : 0.0f;
    if (a1) xT[s1] = val1 ? g1[0] : 0.0f;
    if (a2) xT[s2] = val2 ? g2[0] : 0.0f;
    __syncthreads();

    const int j = tid;                 // hidden unit owned by this thread
    const ull bias2 = pack2(bias_s[j]);

    for (int t = 0; t < Tt; ++t) {
        const int cur = t & 1;
        const float* hcur = hT + cur * (Hh * 8);
        const float* xcur = xT + cur * (48 * 8);

        // Prefetch next-step x (latency hidden behind the FMA loops below)
        float n0 = 0.0f, n1 = 0.0f, n2 = 0.0f;
        if (t + 1 < Tt) {
            const int off = (t + 1) * Ii;
            if (val0) n0 = g0[off];
            if (val1) n1 = g1[off];
            if (val2) n2 = g2[off];
        }

        // Packed accumulators: rows (0,1) (2,3) (4,5) (6,pad)
        ull acc01 = bias2, acc23 = bias2, acc45 = bias2, acc67 = bias2;

        // Input contribution: acc[b] += W_ih[j][i] * x[b][t][i]
        #pragma unroll
        for (int i = 0; i < Ii; ++i) {
            const ull ww = pack2(wih_t[i * Hh + j]);
            const ulonglong2 xa = *reinterpret_cast<const ulonglong2*>(xcur + i * 8);
            const ulonglong2 xb = *reinterpret_cast<const ulonglong2*>(xcur + i * 8 + 4);
            fma2(acc01, ww, xa.x);
            fma2(acc23, ww, xa.y);
            fma2(acc45, ww, xb.x);
            fma2(acc67, ww, xb.y);
        }

        // Recurrent contribution: acc[b] += W_hh[j][k] * h[b][k]
        #pragma unroll 8
        for (int k = 0; k < Hh; ++k) {
            const ull ww = pack2(whh_t[k * Hh + j]);
            const ulonglong2 ha = *reinterpret_cast<const ulonglong2*>(hcur + k * 8);
            const ulonglong2 hb = *reinterpret_cast<const ulonglong2*>(hcur + k * 8 + 4);
            fma2(acc01, ww, ha.x);
            fma2(acc23, ww, ha.y);
            fma2(acc45, ww, hb.x);
            fma2(acc67, ww, hb.y);
        }

        // h_new = tanh(acc); write to the other buffer (transposed [k][b])
        const float2 p01 = unpack2(acc01);
        const float2 p23 = unpack2(acc23);
        const float2 p45 = unpack2(acc45);
        const float2 p67 = unpack2(acc67);
        float4 o1, o2;
        o1.x = tanhf(p01.x); o1.y = tanhf(p01.y);
        o1.z = tanhf(p23.x); o1.w = tanhf(p23.y);
        o2.x = tanhf(p45.x); o2.y = tanhf(p45.y);
        o2.z = tanhf(p67.x); o2.w = 0.0f;           // keep pad lane at 0
        float* hn = hT + (cur ^ 1) * (Hh * 8) + j * 8;
        *reinterpret_cast<float4*>(hn)     = o1;
        *reinterpret_cast<float4*>(hn + 4) = o2;

        // Store prefetched x into the other buffer (pad lanes stay 0)
        float* xn = xT + (cur ^ 1) * (48 * 8);
        if (a0) xn[s0] = n0;
        if (a1) xn[s1] = n1;
        if (a2) xn[s2] = n2;

        __syncthreads();   // one barrier per step: next buffers fully written
    }

    // ---- Final FC: out[b][o] = b_fc[o] + sum_j W_fc[o][j] * h_last[b][j] ----
    // Tt is even, so the last write (t = 511) landed in buffer 0.
    const float* hlast = hT;
    for (int idx = tid; idx < NB * Oo; idx += NTH) {
        const int b = idx / Oo;
        const int o = idx - b * Oo;
        const int row = rowBase + b;
        if (row < Bt) {
            float s = b_fc[o];
            const float* wp = W_fc + o * Hh;
            #pragma unroll 8
            for (int jj = 0; jj < Hh; ++jj)
                s = fmaf(wp[jj], hlast[jj * 8 + b], s);
            out[row * Oo + o] = s;
        }
    }
}

extern "C" void kernel_launch(void* const* d_in, const int* in_sizes, int n_in,
                              void* d_out, int out_size)
{
    const float* x   = (const float*)d_in[0];
    const float* Wih = (const float*)d_in[1];
    const float* bih = (const float*)d_in[2];
    const float* Whh = (const float*)d_in[3];
    const float* bhh = (const float*)d_in[4];
    const float* Wfc = (const float*)d_in[5];
    const float* bfc = (const float*)d_in[6];
    float* out = (float*)d_out;

    cudaFuncSetAttribute(rnn_fused_kernel,
                         cudaFuncAttributeMaxDynamicSharedMemorySize, SMEM_BYTES);
    rnn_fused_kernel<<<NBLK, NTH, SMEM_BYTES>>>(x, Wih, bih, Whh, bhh, Wfc, bfc, out);
}